// round 5
// baseline (speedup 1.0000x reference)
#include <cuda_runtime.h>
#include <cuda_bf16.h>
#include <math.h>

#define NT_   32768
#define B_    16
#define N_    2048
#define INCH_ 128
#define H_    4
#define C_    64
#define HC_   256
#define E_    524288
#define FC0_  1024
#define FC1_  512
#define OMIC_ 128
#define OUT_  2

// ---------------- scratch (static device globals) --------------------------
__device__ __align__(16) float g_xw[NT_ * HC_];
__device__ __align__(16) float g_h [NT_ * HC_];
__device__ __align__(16) float g_asrc[NT_ * 4];
__device__ __align__(16) float g_adst[NT_ * 4];
__device__ int   g_deg[NT_];
__device__ int   g_cur[NT_];
__device__ int   g_row[NT_ + 1];
__device__ int   g_blk[128];
__device__ int   g_blk2[128];
__device__ int   g_csr[E_];
__device__ __align__(16) float g_feat[B_ * 3 * N_];
__device__ __align__(16) float g_part[6 * B_ * FC0_];
__device__ __align__(16) float g_e0[B_ * FC0_];
__device__ __align__(16) float g_e1[B_ * FC1_];
__device__ __align__(16) float g_e2[B_ * OMIC_];
__device__ int   g_i64;

__device__ __forceinline__ float elu1(float x)  { return x > 0.f ? x : (expf(x) - 1.f); }
__device__ __forceinline__ float lrelu(float x) { return x > 0.f ? x : 0.2f * x; }

__device__ __forceinline__ int ld_idx(const void* ei, int i) {
    if (g_i64) return (int)((const long long*)ei)[i];
    return ((const int*)ei)[i];
}

// ---------------- dtype detection (parallel) --------------------------------
__global__ void k_detect(const void* ei) {
    const long long* p64 = (const long long*)ei;
    int t = threadIdx.x;                 // 32 threads
    long long v = p64[t];
    unsigned bad = __ballot_sync(0xffffffffu, v < 0 || v >= NT_);
    if (t == 0) g_i64 = (bad == 0);
}

__global__ void k_zero() {
    int i = blockIdx.x * blockDim.x + threadIdx.x;
    if (i < NT_) { g_deg[i] = 0; g_cur[i] = 0; }
}

// ---------------- CSR build (by dst) ---------------------------------------
__global__ void k_deg(const void* __restrict__ ei) {
    int e = blockIdx.x * blockDim.x + threadIdx.x;
    if (e < E_) atomicAdd(&g_deg[ld_idx(ei, E_ + e) & (NT_ - 1)], 1);
}

__global__ void k_scan1() {            // 128 blocks x 256
    __shared__ int wt[8];
    int t = threadIdx.x;
    int i = blockIdx.x * 256 + t;
    int v = g_deg[i];
    int lane = t & 31, w = t >> 5;
    int inc = v;
#pragma unroll
    for (int off = 1; off < 32; off <<= 1) {
        int u = __shfl_up_sync(0xffffffffu, inc, off);
        if (lane >= off) inc += u;
    }
    if (lane == 31) wt[w] = inc;
    __syncthreads();
    if (t == 0) {
        int run = 0;
#pragma unroll
        for (int k = 0; k < 8; k++) { int x = wt[k]; wt[k] = run; run += x; }
        g_blk[blockIdx.x] = run;
    }
    __syncthreads();
    g_row[i] = inc - v + wt[w];
}

__global__ void k_scan2() {            // 1 block x 128
    __shared__ int wt[4];
    int t = threadIdx.x;
    int v = g_blk[t];
    int lane = t & 31, w = t >> 5;
    int inc = v;
#pragma unroll
    for (int off = 1; off < 32; off <<= 1) {
        int u = __shfl_up_sync(0xffffffffu, inc, off);
        if (lane >= off) inc += u;
    }
    if (lane == 31) wt[w] = inc;
    __syncthreads();
    if (t == 0) {
        int run = 0;
#pragma unroll
        for (int k = 0; k < 4; k++) { int x = wt[k]; wt[k] = run; run += x; }
        g_row[NT_] = run;
    }
    __syncthreads();
    g_blk2[t] = inc - v + wt[w];
}

__global__ void k_scan3() {            // 128 blocks x 256
    int i = blockIdx.x * 256 + threadIdx.x;
    g_row[i] += g_blk2[blockIdx.x];
}

__global__ void k_scatter(const void* __restrict__ ei) {
    int e = blockIdx.x * blockDim.x + threadIdx.x;
    if (e < E_) {
        int d = ld_idx(ei, E_ + e) & (NT_ - 1);
        int s = ld_idx(ei, e) & (NT_ - 1);
        int pos = g_row[d] + atomicAdd(&g_cur[d], 1);
        g_csr[pos] = s;
    }
}

__global__ void k_sortseg() {
    int n = blockIdx.x * blockDim.x + threadIdx.x;
    if (n >= NT_) return;
    int r0 = g_row[n], r1 = g_row[n + 1];
    int len = r1 - r0;
    if (len <= 1) return;
    if (len <= 96) {
        int buf[96];
        for (int i = 0; i < len; i++) buf[i] = g_csr[r0 + i];
        for (int i = 1; i < len; i++) {
            int v = buf[i]; int j = i - 1;
            while (j >= 0 && buf[j] > v) { buf[j + 1] = buf[j]; j--; }
            buf[j + 1] = v;
        }
        for (int i = 0; i < len; i++) g_csr[r0 + i] = buf[i];
    } else {
        for (int i = r0 + 1; i < r1; i++) {
            int v = g_csr[i]; int j = i - 1;
            while (j >= r0 && g_csr[j] > v) { g_csr[j + 1] = g_csr[j]; j--; }
            g_csr[j + 1] = v;
        }
    }
}

// ---------------- bf16 3-pass tensor GEMM: [NT,K]@[K,256] -> g_xw -----------
// block 128x128, 256 thr (8 warps 4x2), warp tile 32x64, k-chunk 32, mma k16
__device__ __forceinline__ void mma16(float* c, const unsigned* a,
                                      unsigned b0, unsigned b1) {
    asm volatile(
        "mma.sync.aligned.m16n8k16.row.col.f32.bf16.bf16.f32 "
        "{%0,%1,%2,%3},{%4,%5,%6,%7},{%8,%9},{%0,%1,%2,%3};"
        : "+f"(c[0]), "+f"(c[1]), "+f"(c[2]), "+f"(c[3])
        : "r"(a[0]), "r"(a[1]), "r"(a[2]), "r"(a[3]), "r"(b0), "r"(b1));
}

__device__ __forceinline__ unsigned pack2(__nv_bfloat16 lo, __nv_bfloat16 hi) {
    __nv_bfloat162 t; t.x = lo; t.y = hi;
    return *(unsigned*)&t;
}

__global__ __launch_bounds__(256, 2)
void k_gemm_tc(const float* __restrict__ Aext, int useH,
               const float* __restrict__ W, int K) {
    const float* A = useH ? (const float*)g_h : Aext;
    __shared__ __nv_bfloat16 AsH[128][40];   // [m][k], pad 40 (20 words: conflict-free)
    __shared__ __nv_bfloat16 AsL[128][40];
    __shared__ __nv_bfloat16 BsH[32][136];   // [k][n], pad 136
    __shared__ __nv_bfloat16 BsL[32][136];
    int tid = threadIdx.x;
    int lid = tid & 31, wid = tid >> 5;
    int wr = wid >> 1, wc = wid & 1;
    int g4 = lid >> 2, t4 = lid & 3;

    const float* Ab = A + (size_t)blockIdx.x * 128 * K;
    const float* Wb = W + blockIdx.y * 128;

    float c[2][8][4];
#pragma unroll
    for (int mt = 0; mt < 2; mt++)
#pragma unroll
        for (int nt = 0; nt < 8; nt++)
#pragma unroll
            for (int q = 0; q < 4; q++) c[mt][nt][q] = 0.f;

    for (int k0 = 0; k0 < K; k0 += 32) {
        // A tile 128x32 -> hi/lo bf16
#pragma unroll
        for (int i = 0; i < 4; i++) {
            int id = tid + 256 * i;
            int row = id >> 3, kq = id & 7;
            float4 v = *(const float4*)(Ab + (size_t)row * K + k0 + kq * 4);
            __nv_bfloat162 h01 = __floats2bfloat162_rn(v.x, v.y);
            __nv_bfloat162 h23 = __floats2bfloat162_rn(v.z, v.w);
            float r0 = v.x - __bfloat162float(h01.x);
            float r1 = v.y - __bfloat162float(h01.y);
            float r2 = v.z - __bfloat162float(h23.x);
            float r3 = v.w - __bfloat162float(h23.y);
            __nv_bfloat162 l01 = __floats2bfloat162_rn(r0, r1);
            __nv_bfloat162 l23 = __floats2bfloat162_rn(r2, r3);
            *(__nv_bfloat162*)&AsH[row][kq * 4]     = h01;
            *(__nv_bfloat162*)&AsH[row][kq * 4 + 2] = h23;
            *(__nv_bfloat162*)&AsL[row][kq * 4]     = l01;
            *(__nv_bfloat162*)&AsL[row][kq * 4 + 2] = l23;
        }
        // B tile 32x128 -> hi/lo bf16 (same [k][n] layout, no transpose)
#pragma unroll
        for (int i = 0; i < 4; i++) {
            int id = tid + 256 * i;
            int kr = id >> 5, nq = id & 31;
            float4 v = *(const float4*)(Wb + (size_t)(k0 + kr) * HC_ + nq * 4);
            __nv_bfloat162 h01 = __floats2bfloat162_rn(v.x, v.y);
            __nv_bfloat162 h23 = __floats2bfloat162_rn(v.z, v.w);
            float r0 = v.x - __bfloat162float(h01.x);
            float r1 = v.y - __bfloat162float(h01.y);
            float r2 = v.z - __bfloat162float(h23.x);
            float r3 = v.w - __bfloat162float(h23.y);
            __nv_bfloat162 l01 = __floats2bfloat162_rn(r0, r1);
            __nv_bfloat162 l23 = __floats2bfloat162_rn(r2, r3);
            *(__nv_bfloat162*)&BsH[kr][nq * 4]     = h01;
            *(__nv_bfloat162*)&BsH[kr][nq * 4 + 2] = h23;
            *(__nv_bfloat162*)&BsL[kr][nq * 4]     = l01;
            *(__nv_bfloat162*)&BsL[kr][nq * 4 + 2] = l23;
        }
        __syncthreads();

#pragma unroll
        for (int ks = 0; ks < 2; ks++) {
            unsigned aH[2][4], aL[2][4];
#pragma unroll
            for (int mt = 0; mt < 2; mt++) {
                int m = wr * 32 + mt * 16 + g4;
                const unsigned* pmH  = (const unsigned*)&AsH[m][0];
                const unsigned* pm8H = (const unsigned*)&AsH[m + 8][0];
                const unsigned* pmL  = (const unsigned*)&AsL[m][0];
                const unsigned* pm8L = (const unsigned*)&AsL[m + 8][0];
                int p = ks * 8 + t4;
                aH[mt][0] = pmH [p];     aH[mt][1] = pm8H[p];
                aH[mt][2] = pmH [p + 4]; aH[mt][3] = pm8H[p + 4];
                aL[mt][0] = pmL [p];     aL[mt][1] = pm8L[p];
                aL[mt][2] = pmL [p + 4]; aL[mt][3] = pm8L[p + 4];
            }
            int kb = ks * 16;
#pragma unroll
            for (int nt = 0; nt < 8; nt++) {
                int n = wc * 64 + nt * 8 + g4;
                unsigned bH0 = pack2(BsH[kb + 2 * t4][n],     BsH[kb + 2 * t4 + 1][n]);
                unsigned bH1 = pack2(BsH[kb + 2 * t4 + 8][n], BsH[kb + 2 * t4 + 9][n]);
                unsigned bL0 = pack2(BsL[kb + 2 * t4][n],     BsL[kb + 2 * t4 + 1][n]);
                unsigned bL1 = pack2(BsL[kb + 2 * t4 + 8][n], BsL[kb + 2 * t4 + 9][n]);
#pragma unroll
                for (int mt = 0; mt < 2; mt++) {
                    mma16(c[mt][nt], aH[mt], bH0, bH1);   // hi*hi
                    mma16(c[mt][nt], aL[mt], bH0, bH1);   // lo*hi
                    mma16(c[mt][nt], aH[mt], bL0, bL1);   // hi*lo
                }
            }
        }
        __syncthreads();
    }

#pragma unroll
    for (int mt = 0; mt < 2; mt++) {
#pragma unroll
        for (int nt = 0; nt < 8; nt++) {
            int row = blockIdx.x * 128 + wr * 32 + mt * 16 + g4;
            int col = blockIdx.y * 128 + wc * 64 + nt * 8 + 2 * t4;
            float2 v0 = {c[mt][nt][0], c[mt][nt][1]};
            float2 v1 = {c[mt][nt][2], c[mt][nt][3]};
            *(float2*)(g_xw + (size_t)row * HC_ + col)       = v0;
            *(float2*)(g_xw + (size_t)(row + 8) * HC_ + col) = v1;
        }
    }
}

// ---------------- attention dots -------------------------------------------
__global__ void k_attn(const float* __restrict__ att_s,
                       const float* __restrict__ att_d) {
    int gw = (blockIdx.x * blockDim.x + threadIdx.x) >> 5;
    int lane = threadIdx.x & 31;
    if (gw >= NT_) return;
    const float4* xp = (const float4*)(g_xw + (size_t)gw * HC_ + lane * 8);
    const float4* sp = (const float4*)(att_s + lane * 8);
    const float4* dp = (const float4*)(att_d + lane * 8);
    float4 x0 = xp[0], x1 = xp[1];
    float4 s0 = sp[0], s1 = sp[1];
    float4 d0 = dp[0], d1 = dp[1];
    float ps = x0.x*s0.x + x0.y*s0.y + x0.z*s0.z + x0.w*s0.w
             + x1.x*s1.x + x1.y*s1.y + x1.z*s1.z + x1.w*s1.w;
    float pd = x0.x*d0.x + x0.y*d0.y + x0.z*d0.z + x0.w*d0.w
             + x1.x*d1.x + x1.y*d1.y + x1.z*d1.z + x1.w*d1.w;
#pragma unroll
    for (int off = 4; off >= 1; off >>= 1) {
        ps += __shfl_down_sync(0xffffffffu, ps, off);
        pd += __shfl_down_sync(0xffffffffu, pd, off);
    }
    if ((lane & 7) == 0) {
        int h = lane >> 3;
        g_asrc[gw * 4 + h] = ps;
        g_adst[gw * 4 + h] = pd;
    }
}

// ---------------- GAT aggregation (single pass, unroll 4) -------------------
__global__ void k_agg(const float* __restrict__ bias,
                      const float* __restrict__ poolw,
                      const float* __restrict__ poolb,
                      int writeH, int seg) {
    int n = (blockIdx.x * blockDim.x + threadIdx.x) >> 5;
    int lane = threadIdx.x & 31;
    if (n >= NT_) return;
    int h = lane >> 3;

    float4 d4 = *(const float4*)(g_adst + n * 4);
    float4 s4 = *(const float4*)(g_asrc + n * 4);
    float adh = (h == 0) ? d4.x : (h == 1) ? d4.y : (h == 2) ? d4.z : d4.w;
    float ash = (h == 0) ? s4.x : (h == 1) ? s4.y : (h == 2) ? s4.z : s4.w;

    int r0 = g_row[n], r1 = g_row[n + 1];

    float wself = __expf(lrelu(ash + adh));
    float den = wself;
    const float4* xp = (const float4*)(g_xw + (size_t)n * HC_ + lane * 8);
    float4 q0 = xp[0], q1 = xp[1];
    float4 acc0 = {wself*q0.x, wself*q0.y, wself*q0.z, wself*q0.w};
    float4 acc1 = {wself*q1.x, wself*q1.y, wself*q1.z, wself*q1.w};

    int e = r0;
    for (; e + 4 <= r1; e += 4) {
        int s0 = g_csr[e], s1 = g_csr[e + 1], s2 = g_csr[e + 2], s3 = g_csr[e + 3];
        float as0 = g_asrc[s0 * 4 + h];
        float as1 = g_asrc[s1 * 4 + h];
        float as2 = g_asrc[s2 * 4 + h];
        float as3 = g_asrc[s3 * 4 + h];
        const float4* p0 = (const float4*)(g_xw + (size_t)s0 * HC_ + lane * 8);
        const float4* p1 = (const float4*)(g_xw + (size_t)s1 * HC_ + lane * 8);
        const float4* p2 = (const float4*)(g_xw + (size_t)s2 * HC_ + lane * 8);
        const float4* p3 = (const float4*)(g_xw + (size_t)s3 * HC_ + lane * 8);
        float4 a0 = p0[0], b0 = p0[1];
        float4 a1 = p1[0], b1 = p1[1];
        float4 a2 = p2[0], b2 = p2[1];
        float4 a3 = p3[0], b3 = p3[1];
        float w0 = __expf(lrelu(as0 + adh));
        float w1 = __expf(lrelu(as1 + adh));
        float w2 = __expf(lrelu(as2 + adh));
        float w3 = __expf(lrelu(as3 + adh));
        den += w0 + w1 + w2 + w3;
        acc0.x += w0*a0.x + w1*a1.x + w2*a2.x + w3*a3.x;
        acc0.y += w0*a0.y + w1*a1.y + w2*a2.y + w3*a3.y;
        acc0.z += w0*a0.z + w1*a1.z + w2*a2.z + w3*a3.z;
        acc0.w += w0*a0.w + w1*a1.w + w2*a2.w + w3*a3.w;
        acc1.x += w0*b0.x + w1*b1.x + w2*b2.x + w3*b3.x;
        acc1.y += w0*b0.y + w1*b1.y + w2*b2.y + w3*b3.y;
        acc1.z += w0*b0.z + w1*b1.z + w2*b2.z + w3*b3.z;
        acc1.w += w0*b0.w + w1*b1.w + w2*b2.w + w3*b3.w;
    }
    for (; e < r1; e++) {
        int s = g_csr[e];
        float as = g_asrc[s * 4 + h];
        float wgt = __expf(lrelu(as + adh));
        den += wgt;
        const float4* q = (const float4*)(g_xw + (size_t)s * HC_ + lane * 8);
        float4 a = q[0], b = q[1];
        acc0.x += wgt * a.x; acc0.y += wgt * a.y;
        acc0.z += wgt * a.z; acc0.w += wgt * a.w;
        acc1.x += wgt * b.x; acc1.y += wgt * b.y;
        acc1.z += wgt * b.z; acc1.w += wgt * b.w;
    }
    float rden = 1.f / (den + 1e-16f);
    acc0.x *= rden; acc0.y *= rden; acc0.z *= rden; acc0.w *= rden;
    acc1.x *= rden; acc1.y *= rden; acc1.z *= rden; acc1.w *= rden;

    const float* bp = bias + lane * 8;
    float v[8];
    v[0] = elu1(acc0.x + bp[0]); v[1] = elu1(acc0.y + bp[1]);
    v[2] = elu1(acc0.z + bp[2]); v[3] = elu1(acc0.w + bp[3]);
    v[4] = elu1(acc1.x + bp[4]); v[5] = elu1(acc1.y + bp[5]);
    v[6] = elu1(acc1.z + bp[6]); v[7] = elu1(acc1.w + bp[7]);

    if (writeH) {
        float4 o0 = {v[0], v[1], v[2], v[3]};
        float4 o1 = {v[4], v[5], v[6], v[7]};
        *(float4*)(g_h + (size_t)n * HC_ + lane * 8)     = o0;
        *(float4*)(g_h + (size_t)n * HC_ + lane * 8 + 4) = o1;
    }

    const float* pw = poolw + lane * 8;
    float p = v[0]*pw[0] + v[1]*pw[1] + v[2]*pw[2] + v[3]*pw[3]
            + v[4]*pw[4] + v[5]*pw[5] + v[6]*pw[6] + v[7]*pw[7];
#pragma unroll
    for (int off = 16; off >= 1; off >>= 1)
        p += __shfl_xor_sync(0xffffffffu, p, off);
    if (lane == 0)
        g_feat[(n >> 11) * (3 * N_) + seg * N_ + (n & 2047)] = p + poolb[0];
}

// ---------------- x0: per-node mean ----------------------------------------
__global__ void k_x0(const float* __restrict__ x) {
    int n = (blockIdx.x * blockDim.x + threadIdx.x) >> 5;
    int lane = threadIdx.x & 31;
    if (n >= NT_) return;
    float4 v = *(const float4*)(x + (size_t)n * INCH_ + lane * 4);
    float s = v.x + v.y + v.z + v.w;
#pragma unroll
    for (int off = 16; off >= 1; off >>= 1)
        s += __shfl_xor_sync(0xffffffffu, s, off);
    if (lane == 0)
        g_feat[(n >> 11) * (3 * N_) + (n & 2047)] = s * (1.f / 128.f);
}

// ---------------- LayerNorm in place ----------------------------------------
__global__ void k_ln(const float* __restrict__ w, const float* __restrict__ b) {
    __shared__ float red[8];
    __shared__ float tot;
    int row = blockIdx.x;
    float* p = g_feat + (row / 3) * (3 * N_) + (row % 3) * N_;
    int t = threadIdx.x;
    float v[8];
    float s = 0.f;
#pragma unroll
    for (int i = 0; i < 8; i++) { v[i] = p[t + 256 * i]; s += v[i]; }
#pragma unroll
    for (int off = 16; off >= 1; off >>= 1) s += __shfl_xor_sync(0xffffffffu, s, off);
    if ((t & 31) == 0) red[t >> 5] = s;
    __syncthreads();
    if (t == 0) { float z = 0.f; for (int i = 0; i < 8; i++) z += red[i]; tot = z; }
    __syncthreads();
    float mu = tot * (1.f / 2048.f);
    float q = 0.f;
#pragma unroll
    for (int i = 0; i < 8; i++) { float d = v[i] - mu; q += d * d; }
#pragma unroll
    for (int off = 16; off >= 1; off >>= 1) q += __shfl_xor_sync(0xffffffffu, q, off);
    __syncthreads();
    if ((t & 31) == 0) red[t >> 5] = q;
    __syncthreads();
    if (t == 0) { float z = 0.f; for (int i = 0; i < 8; i++) z += red[i]; tot = z; }
    __syncthreads();
    float r = rsqrtf(tot * (1.f / 2048.f) + 1e-5f);
#pragma unroll
    for (int i = 0; i < 8; i++) {
        int idx = t + 256 * i;
        p[idx] = (v[i] - mu) * r * w[idx] + b[idx];
    }
}

// ---------------- FC partial GEMM (deterministic k-splits) -------------------
__global__ void k_fc(int which, const float* __restrict__ W, int K, int Ncol) {
    const float* A = (which == 0) ? (const float*)g_feat
                   : (which == 1) ? (const float*)g_e0 : (const float*)g_e1;
    __shared__ float sa[16][128];
    int tid = threadIdx.x;
    int j = blockIdx.x * 128 + tid;
    int kslab = K / gridDim.y;
    int k0 = blockIdx.y * kslab;
    float acc[16];
#pragma unroll
    for (int bi = 0; bi < 16; bi++) acc[bi] = 0.f;
    for (int kt = k0; kt < k0 + kslab; kt += 128) {
#pragma unroll
        for (int i = 0; i < 16; i++) sa[i][tid] = A[i * K + kt + tid];
        __syncthreads();
#pragma unroll 4
        for (int kk = 0; kk < 128; kk++) {
            float wv = W[(size_t)(kt + kk) * Ncol + j];
#pragma unroll
            for (int bi = 0; bi < 16; bi++) acc[bi] += sa[bi][kk] * wv;
        }
        __syncthreads();
    }
#pragma unroll
    for (int bi = 0; bi < 16; bi++)
        g_part[((size_t)blockIdx.y * 16 + bi) * Ncol + j] = acc[bi];
}

__global__ void k_fcsum(int which, const float* __restrict__ bias,
                        int Ncol, int nsplit) {
    float* C = (which == 0) ? g_e0 : (which == 1) ? g_e1 : g_e2;
    int i = blockIdx.x * blockDim.x + threadIdx.x;
    if (i < 16 * Ncol) {
        float s = 0.f;
        for (int p = 0; p < nsplit; p++) s += g_part[(size_t)p * 16 * Ncol + i];
        C[i] = elu1(s + bias[i % Ncol]);
    }
}

__global__ void k_last(const float* __restrict__ lw, const float* __restrict__ lb,
                       float* __restrict__ out, int out_n) {
    int t = threadIdx.x;
    if (t < 32 && t < out_n) {
        int bi = t >> 1, o = t & 1;
        float a = 0.f;
        for (int k = 0; k < OMIC_; k++) a += g_e2[bi * OMIC_ + k] * lw[k * 2 + o];
        out[t] = a + lb[o];
    }
}

// ---------------- driver -----------------------------------------------------
extern "C" void kernel_launch(void* const* d_in, const int* in_sizes, int n_in,
                              void* d_out, int out_size) {
    const float* x   = (const float*)d_in[0];
    const void*  ei  = d_in[1];
    const float* w1  = (const float*)d_in[2];
    const float* as1 = (const float*)d_in[3];
    const float* ad1 = (const float*)d_in[4];
    const float* b1  = (const float*)d_in[5];
    const float* p1w = (const float*)d_in[6];
    const float* p1b = (const float*)d_in[7];
    const float* w2  = (const float*)d_in[8];
    const float* as2 = (const float*)d_in[9];
    const float* ad2 = (const float*)d_in[10];
    const float* b2  = (const float*)d_in[11];
    const float* p2w = (const float*)d_in[12];
    const float* p2b = (const float*)d_in[13];
    const float* lnw = (const float*)d_in[14];
    const float* lnb = (const float*)d_in[15];
    const float* e0w = (const float*)d_in[16];
    const float* e0b = (const float*)d_in[17];
    const float* e1w = (const float*)d_in[18];
    const float* e1b = (const float*)d_in[19];
    const float* e2w = (const float*)d_in[20];
    const float* e2b = (const float*)d_in[21];
    const float* lw  = (const float*)d_in[22];
    const float* lb  = (const float*)d_in[23];
    float* out = (float*)d_out;

    k_detect<<<1, 32>>>(ei);                                   // 1
    k_zero<<<128, 256>>>();                                    // 2
    k_deg<<<E_ / 256, 256>>>(ei);                              // 3
    k_gemm_tc<<<dim3(NT_ / 128, 2), 256>>>(x, 0, w1, INCH_);   // 4 <- profiled
    k_scan1<<<128, 256>>>();                                   // 5
    k_scan2<<<1, 128>>>();                                     // 6
    k_scan3<<<128, 256>>>();                                   // 7
    k_scatter<<<E_ / 256, 256>>>(ei);                          // 8
    k_sortseg<<<NT_ / 256, 256>>>();                           // 9
    k_attn<<<NT_ / 8, 256>>>(as1, ad1);                        // 10
    k_agg<<<NT_ / 8, 256>>>(b1, p1w, p1b, 1, 1);               // 11

    k_gemm_tc<<<dim3(NT_ / 128, 2), 256>>>(nullptr, 1, w2, HC_);
    k_attn<<<NT_ / 8, 256>>>(as2, ad2);
    k_agg<<<NT_ / 8, 256>>>(b2, p2w, p2b, 0, 2);

    k_x0<<<NT_ / 8, 256>>>(x);
    k_ln<<<48, 256>>>(lnw, lnb);

    k_fc<<<dim3(FC0_ / 128, 6), 128>>>(0, e0w, 3 * N_, FC0_);
    k_fcsum<<<(16 * FC0_ + 255) / 256, 256>>>(0, e0b, FC0_, 6);
    k_fc<<<dim3(FC1_ / 128, 2), 128>>>(1, e1w, FC0_, FC1_);
    k_fcsum<<<(16 * FC1_ + 255) / 256, 256>>>(1, e1b, FC1_, 2);
    k_fc<<<dim3(OMIC_ / 128, 4), 128>>>(2, e2w, FC1_, OMIC_);
    k_fcsum<<<(16 * OMIC_ + 255) / 256, 256>>>(2, e2b, OMIC_, 4);
    k_last<<<1, 32>>>(lw, lb, out, out_size);
}

// round 6
// speedup vs baseline: 2.2618x; 2.2618x over previous
#include <cuda_runtime.h>
#include <cuda_bf16.h>
#include <math.h>

#define NT_   32768
#define B_    16
#define N_    2048
#define INCH_ 128
#define H_    4
#define C_    64
#define HC_   256
#define E_    524288
#define FC0_  1024
#define FC1_  512
#define OMIC_ 128
#define OUT_  2

// ---------------- scratch (static device globals) --------------------------
__device__ __align__(16) float g_xw[NT_ * HC_];
__device__ __align__(16) float g_h [NT_ * HC_];
__device__ __align__(16) float g_asrc[NT_ * 4];
__device__ __align__(16) float g_adst[NT_ * 4];
__device__ int   g_deg[NT_];
__device__ int   g_cur[NT_];
__device__ int   g_row[NT_ + 1];
__device__ int   g_blk[128];
__device__ int   g_blk2[128];
__device__ int   g_csr[E_];
__device__ __align__(16) float g_feat[B_ * 3 * N_];
__device__ __align__(16) float g_part[12 * B_ * FC0_];
__device__ __align__(16) float g_e0[B_ * FC0_];
__device__ __align__(16) float g_e1[B_ * FC1_];
__device__ __align__(16) float g_e2[B_ * OMIC_];
__device__ int   g_i64;

__device__ __forceinline__ float elu1(float x)  { return x > 0.f ? x : (expf(x) - 1.f); }
__device__ __forceinline__ float lrelu(float x) { return x > 0.f ? x : 0.2f * x; }

__device__ __forceinline__ int ld_idx(const void* ei, int i) {
    if (g_i64) return (int)((const long long*)ei)[i];
    return ((const int*)ei)[i];
}

// ---------------- dtype detection -------------------------------------------
__global__ void k_detect(const void* ei) {
    const long long* p64 = (const long long*)ei;
    int t = threadIdx.x;
    long long v = p64[t];
    unsigned bad = __ballot_sync(0xffffffffu, v < 0 || v >= NT_);
    if (t == 0) g_i64 = (bad == 0);
}

__global__ void k_zero() {
    int i = blockIdx.x * blockDim.x + threadIdx.x;
    if (i < NT_) { g_deg[i] = 0; g_cur[i] = 0; }
}

// ---------------- CSR build (by dst) ----------------------------------------
__global__ void k_deg(const void* __restrict__ ei) {
    int e = blockIdx.x * blockDim.x + threadIdx.x;
    if (e < E_) atomicAdd(&g_deg[ld_idx(ei, E_ + e) & (NT_ - 1)], 1);
}

__global__ void k_scan1() {
    __shared__ int wt[8];
    int t = threadIdx.x;
    int i = blockIdx.x * 256 + t;
    int v = g_deg[i];
    int lane = t & 31, w = t >> 5;
    int inc = v;
#pragma unroll
    for (int off = 1; off < 32; off <<= 1) {
        int u = __shfl_up_sync(0xffffffffu, inc, off);
        if (lane >= off) inc += u;
    }
    if (lane == 31) wt[w] = inc;
    __syncthreads();
    if (t == 0) {
        int run = 0;
#pragma unroll
        for (int k = 0; k < 8; k++) { int x = wt[k]; wt[k] = run; run += x; }
        g_blk[blockIdx.x] = run;
    }
    __syncthreads();
    g_row[i] = inc - v + wt[w];
}

__global__ void k_scan2() {
    __shared__ int wt[4];
    int t = threadIdx.x;
    int v = g_blk[t];
    int lane = t & 31, w = t >> 5;
    int inc = v;
#pragma unroll
    for (int off = 1; off < 32; off <<= 1) {
        int u = __shfl_up_sync(0xffffffffu, inc, off);
        if (lane >= off) inc += u;
    }
    if (lane == 31) wt[w] = inc;
    __syncthreads();
    if (t == 0) {
        int run = 0;
#pragma unroll
        for (int k = 0; k < 4; k++) { int x = wt[k]; wt[k] = run; run += x; }
        g_row[NT_] = run;
    }
    __syncthreads();
    g_blk2[t] = inc - v + wt[w];
}

__global__ void k_scan3() {
    int i = blockIdx.x * 256 + threadIdx.x;
    g_row[i] += g_blk2[blockIdx.x];
}

__global__ void k_scatter(const void* __restrict__ ei) {
    int e = blockIdx.x * blockDim.x + threadIdx.x;
    if (e < E_) {
        int d = ld_idx(ei, E_ + e) & (NT_ - 1);
        int s = ld_idx(ei, e) & (NT_ - 1);
        int pos = g_row[d] + atomicAdd(&g_cur[d], 1);
        g_csr[pos] = s;
    }
}

__global__ void k_sortseg() {
    int n = blockIdx.x * blockDim.x + threadIdx.x;
    if (n >= NT_) return;
    int r0 = g_row[n], r1 = g_row[n + 1];
    int len = r1 - r0;
    if (len <= 1) return;
    if (len <= 96) {
        int buf[96];
        for (int i = 0; i < len; i++) buf[i] = g_csr[r0 + i];
        for (int i = 1; i < len; i++) {
            int v = buf[i]; int j = i - 1;
            while (j >= 0 && buf[j] > v) { buf[j + 1] = buf[j]; j--; }
            buf[j + 1] = v;
        }
        for (int i = 0; i < len; i++) g_csr[r0 + i] = buf[i];
    } else {
        for (int i = r0 + 1; i < r1; i++) {
            int v = g_csr[i]; int j = i - 1;
            while (j >= r0 && g_csr[j] > v) { g_csr[j + 1] = g_csr[j]; j--; }
            g_csr[j + 1] = v;
        }
    }
}

// ---------------- bf16 3-pass tensor GEMM with ldmatrix ---------------------
__device__ __forceinline__ void mma16(float* c, const unsigned* a,
                                      unsigned b0, unsigned b1) {
    asm volatile(
        "mma.sync.aligned.m16n8k16.row.col.f32.bf16.bf16.f32 "
        "{%0,%1,%2,%3},{%4,%5,%6,%7},{%8,%9},{%0,%1,%2,%3};"
        : "+f"(c[0]), "+f"(c[1]), "+f"(c[2]), "+f"(c[3])
        : "r"(a[0]), "r"(a[1]), "r"(a[2]), "r"(a[3]), "r"(b0), "r"(b1));
}

__device__ __forceinline__ unsigned sptr(const void* p) {
    return (unsigned)__cvta_generic_to_shared(p);
}

__device__ __forceinline__ void ldsm4(unsigned* r, unsigned addr) {
    asm volatile("ldmatrix.sync.aligned.m8n8.x4.shared.b16 {%0,%1,%2,%3}, [%4];"
                 : "=r"(r[0]), "=r"(r[1]), "=r"(r[2]), "=r"(r[3]) : "r"(addr));
}

__device__ __forceinline__ void ldsm4t(unsigned* r, unsigned addr) {
    asm volatile("ldmatrix.sync.aligned.m8n8.x4.trans.shared.b16 {%0,%1,%2,%3}, [%4];"
                 : "=r"(r[0]), "=r"(r[1]), "=r"(r[2]), "=r"(r[3]) : "r"(addr));
}

__global__ __launch_bounds__(256, 2)
void k_gemm_tc(const float* __restrict__ Aext, int useH,
               const float* __restrict__ W, int K) {
    const float* A = useH ? (const float*)g_h : Aext;
    __shared__ __nv_bfloat16 AsH[128][40];   // stride 80B: 16B-aligned, LDSM conflict-free
    __shared__ __nv_bfloat16 AsL[128][40];
    __shared__ __nv_bfloat16 BsH[32][136];   // stride 272B
    __shared__ __nv_bfloat16 BsL[32][136];
    int tid = threadIdx.x;
    int lid = tid & 31, wid = tid >> 5;
    int wr = wid >> 1, wc = wid & 1;
    int lrow = lid & 7, seg = lid >> 3;

    const float* Ab = A + (size_t)blockIdx.x * 128 * K;
    const float* Wb = W + blockIdx.y * 128;

    float c[2][8][4];
#pragma unroll
    for (int mt = 0; mt < 2; mt++)
#pragma unroll
        for (int nt = 0; nt < 8; nt++)
#pragma unroll
            for (int q = 0; q < 4; q++) c[mt][nt][q] = 0.f;

    for (int k0 = 0; k0 < K; k0 += 32) {
        // A tile 128x32 -> hi/lo bf16
#pragma unroll
        for (int i = 0; i < 4; i++) {
            int id = tid + 256 * i;
            int row = id >> 3, kq = id & 7;
            float4 v = *(const float4*)(Ab + (size_t)row * K + k0 + kq * 4);
            __nv_bfloat162 h01 = __floats2bfloat162_rn(v.x, v.y);
            __nv_bfloat162 h23 = __floats2bfloat162_rn(v.z, v.w);
            __nv_bfloat162 l01 = __floats2bfloat162_rn(v.x - __bfloat162float(h01.x),
                                                       v.y - __bfloat162float(h01.y));
            __nv_bfloat162 l23 = __floats2bfloat162_rn(v.z - __bfloat162float(h23.x),
                                                       v.w - __bfloat162float(h23.y));
            *(__nv_bfloat162*)&AsH[row][kq * 4]     = h01;
            *(__nv_bfloat162*)&AsH[row][kq * 4 + 2] = h23;
            *(__nv_bfloat162*)&AsL[row][kq * 4]     = l01;
            *(__nv_bfloat162*)&AsL[row][kq * 4 + 2] = l23;
        }
        // B tile 32x128 -> hi/lo bf16
#pragma unroll
        for (int i = 0; i < 4; i++) {
            int id = tid + 256 * i;
            int kr = id >> 5, nq = id & 31;
            float4 v = *(const float4*)(Wb + (size_t)(k0 + kr) * HC_ + nq * 4);
            __nv_bfloat162 h01 = __floats2bfloat162_rn(v.x, v.y);
            __nv_bfloat162 h23 = __floats2bfloat162_rn(v.z, v.w);
            __nv_bfloat162 l01 = __floats2bfloat162_rn(v.x - __bfloat162float(h01.x),
                                                       v.y - __bfloat162float(h01.y));
            __nv_bfloat162 l23 = __floats2bfloat162_rn(v.z - __bfloat162float(h23.x),
                                                       v.w - __bfloat162float(h23.y));
            *(__nv_bfloat162*)&BsH[kr][nq * 4]     = h01;
            *(__nv_bfloat162*)&BsH[kr][nq * 4 + 2] = h23;
            *(__nv_bfloat162*)&BsL[kr][nq * 4]     = l01;
            *(__nv_bfloat162*)&BsL[kr][nq * 4 + 2] = l23;
        }
        __syncthreads();

#pragma unroll
        for (int ks = 0; ks < 2; ks++) {
            int kc = ks * 16;
            // A fragments: mats {m0-7,m8-15} x {k0-7,k8-15}
            unsigned aH[2][4], aL[2][4];
            int ar = (seg & 1) * 8 + lrow;
            int ac = kc + (seg >> 1) * 8;
#pragma unroll
            for (int mt = 0; mt < 2; mt++) {
                int m = wr * 32 + mt * 16 + ar;
                ldsm4(aH[mt], sptr(&AsH[m][ac]));
                ldsm4(aL[mt], sptr(&AsL[m][ac]));
            }
            int br = kc + (seg & 1) * 8 + lrow;
            int bcoff = (seg >> 1) * 8;
#pragma unroll
            for (int ntp = 0; ntp < 4; ntp++) {
                int n0 = wc * 64 + ntp * 16 + bcoff;
                unsigned bH[4], bL[4];
                ldsm4t(bH, sptr(&BsH[br][n0]));
                ldsm4t(bL, sptr(&BsL[br][n0]));
#pragma unroll
                for (int half = 0; half < 2; half++) {
                    int nt = 2 * ntp + half;
                    unsigned b0H = bH[2 * half], b1H = bH[2 * half + 1];
                    unsigned b0L = bL[2 * half], b1L = bL[2 * half + 1];
#pragma unroll
                    for (int mt = 0; mt < 2; mt++) {
                        mma16(c[mt][nt], aH[mt], b0H, b1H);
                        mma16(c[mt][nt], aL[mt], b0H, b1H);
                        mma16(c[mt][nt], aH[mt], b0L, b1L);
                    }
                }
            }
        }
        __syncthreads();
    }

    int g4 = lid >> 2, t4 = lid & 3;
#pragma unroll
    for (int mt = 0; mt < 2; mt++) {
#pragma unroll
        for (int nt = 0; nt < 8; nt++) {
            int row = blockIdx.x * 128 + wr * 32 + mt * 16 + g4;
            int col = blockIdx.y * 128 + wc * 64 + nt * 8 + 2 * t4;
            float2 v0 = {c[mt][nt][0], c[mt][nt][1]};
            float2 v1 = {c[mt][nt][2], c[mt][nt][3]};
            *(float2*)(g_xw + (size_t)row * HC_ + col)       = v0;
            *(float2*)(g_xw + (size_t)(row + 8) * HC_ + col) = v1;
        }
    }
}

// ---------------- attention dots --------------------------------------------
__global__ void k_attn(const float* __restrict__ att_s,
                       const float* __restrict__ att_d) {
    int gw = (blockIdx.x * blockDim.x + threadIdx.x) >> 5;
    int lane = threadIdx.x & 31;
    if (gw >= NT_) return;
    const float4* xp = (const float4*)(g_xw + (size_t)gw * HC_ + lane * 8);
    const float4* sp = (const float4*)(att_s + lane * 8);
    const float4* dp = (const float4*)(att_d + lane * 8);
    float4 x0 = xp[0], x1 = xp[1];
    float4 s0 = sp[0], s1 = sp[1];
    float4 d0 = dp[0], d1 = dp[1];
    float ps = x0.x*s0.x + x0.y*s0.y + x0.z*s0.z + x0.w*s0.w
             + x1.x*s1.x + x1.y*s1.y + x1.z*s1.z + x1.w*s1.w;
    float pd = x0.x*d0.x + x0.y*d0.y + x0.z*d0.z + x0.w*d0.w
             + x1.x*d1.x + x1.y*d1.y + x1.z*d1.z + x1.w*d1.w;
#pragma unroll
    for (int off = 4; off >= 1; off >>= 1) {
        ps += __shfl_down_sync(0xffffffffu, ps, off);
        pd += __shfl_down_sync(0xffffffffu, pd, off);
    }
    if ((lane & 7) == 0) {
        int h = lane >> 3;
        g_asrc[gw * 4 + h] = ps;
        g_adst[gw * 4 + h] = pd;
    }
}

// ---------------- GAT aggregation (single pass, simple loop) -----------------
__global__ void k_agg(const float* __restrict__ bias,
                      const float* __restrict__ poolw,
                      const float* __restrict__ poolb,
                      int writeH, int seg) {
    int n = (blockIdx.x * blockDim.x + threadIdx.x) >> 5;
    int lane = threadIdx.x & 31;
    if (n >= NT_) return;
    int h = lane >> 3;

    float4 d4 = *(const float4*)(g_adst + n * 4);
    float4 s4 = *(const float4*)(g_asrc + n * 4);
    float adh = (h == 0) ? d4.x : (h == 1) ? d4.y : (h == 2) ? d4.z : d4.w;
    float ash = (h == 0) ? s4.x : (h == 1) ? s4.y : (h == 2) ? s4.z : s4.w;

    int r0 = g_row[n], r1 = g_row[n + 1];

    float wself = __expf(lrelu(ash + adh));
    float den = wself;
    const float4* xp = (const float4*)(g_xw + (size_t)n * HC_ + lane * 8);
    float4 q0 = xp[0], q1 = xp[1];
    float4 acc0 = {wself*q0.x, wself*q0.y, wself*q0.z, wself*q0.w};
    float4 acc1 = {wself*q1.x, wself*q1.y, wself*q1.z, wself*q1.w};

    for (int e = r0; e < r1; e++) {
        int s = g_csr[e];
        float as = g_asrc[s * 4 + h];
        float wgt = __expf(lrelu(as + adh));
        den += wgt;
        const float4* q = (const float4*)(g_xw + (size_t)s * HC_ + lane * 8);
        float4 a = q[0], b = q[1];
        acc0.x += wgt * a.x; acc0.y += wgt * a.y;
        acc0.z += wgt * a.z; acc0.w += wgt * a.w;
        acc1.x += wgt * b.x; acc1.y += wgt * b.y;
        acc1.z += wgt * b.z; acc1.w += wgt * b.w;
    }
    float rden = 1.f / (den + 1e-16f);
    acc0.x *= rden; acc0.y *= rden; acc0.z *= rden; acc0.w *= rden;
    acc1.x *= rden; acc1.y *= rden; acc1.z *= rden; acc1.w *= rden;

    const float* bp = bias + lane * 8;
    float v[8];
    v[0] = elu1(acc0.x + bp[0]); v[1] = elu1(acc0.y + bp[1]);
    v[2] = elu1(acc0.z + bp[2]); v[3] = elu1(acc0.w + bp[3]);
    v[4] = elu1(acc1.x + bp[4]); v[5] = elu1(acc1.y + bp[5]);
    v[6] = elu1(acc1.z + bp[6]); v[7] = elu1(acc1.w + bp[7]);

    if (writeH) {
        float4 o0 = {v[0], v[1], v[2], v[3]};
        float4 o1 = {v[4], v[5], v[6], v[7]};
        *(float4*)(g_h + (size_t)n * HC_ + lane * 8)     = o0;
        *(float4*)(g_h + (size_t)n * HC_ + lane * 8 + 4) = o1;
    }

    const float* pw = poolw + lane * 8;
    float p = v[0]*pw[0] + v[1]*pw[1] + v[2]*pw[2] + v[3]*pw[3]
            + v[4]*pw[4] + v[5]*pw[5] + v[6]*pw[6] + v[7]*pw[7];
#pragma unroll
    for (int off = 16; off >= 1; off >>= 1)
        p += __shfl_xor_sync(0xffffffffu, p, off);
    if (lane == 0)
        g_feat[(n >> 11) * (3 * N_) + seg * N_ + (n & 2047)] = p + poolb[0];
}

// ---------------- x0: per-node mean -----------------------------------------
__global__ void k_x0(const float* __restrict__ x) {
    int n = (blockIdx.x * blockDim.x + threadIdx.x) >> 5;
    int lane = threadIdx.x & 31;
    if (n >= NT_) return;
    float4 v = *(const float4*)(x + (size_t)n * INCH_ + lane * 4);
    float s = v.x + v.y + v.z + v.w;
#pragma unroll
    for (int off = 16; off >= 1; off >>= 1)
        s += __shfl_xor_sync(0xffffffffu, s, off);
    if (lane == 0)
        g_feat[(n >> 11) * (3 * N_) + (n & 2047)] = s * (1.f / 128.f);
}

// ---------------- LayerNorm in place -----------------------------------------
__global__ void k_ln(const float* __restrict__ w, const float* __restrict__ b) {
    __shared__ float red[8];
    __shared__ float tot;
    int row = blockIdx.x;
    float* p = g_feat + (row / 3) * (3 * N_) + (row % 3) * N_;
    int t = threadIdx.x;
    float v[8];
    float s = 0.f;
#pragma unroll
    for (int i = 0; i < 8; i++) { v[i] = p[t + 256 * i]; s += v[i]; }
#pragma unroll
    for (int off = 16; off >= 1; off >>= 1) s += __shfl_xor_sync(0xffffffffu, s, off);
    if ((t & 31) == 0) red[t >> 5] = s;
    __syncthreads();
    if (t == 0) { float z = 0.f; for (int i = 0; i < 8; i++) z += red[i]; tot = z; }
    __syncthreads();
    float mu = tot * (1.f / 2048.f);
    float q = 0.f;
#pragma unroll
    for (int i = 0; i < 8; i++) { float d = v[i] - mu; q += d * d; }
#pragma unroll
    for (int off = 16; off >= 1; off >>= 1) q += __shfl_xor_sync(0xffffffffu, q, off);
    __syncthreads();
    if ((t & 31) == 0) red[t >> 5] = q;
    __syncthreads();
    if (t == 0) { float z = 0.f; for (int i = 0; i < 8; i++) z += red[i]; tot = z; }
    __syncthreads();
    float r = rsqrtf(tot * (1.f / 2048.f) + 1e-5f);
#pragma unroll
    for (int i = 0; i < 8; i++) {
        int idx = t + 256 * i;
        p[idx] = (v[i] - mu) * r * w[idx] + b[idx];
    }
}

// ---------------- FC partial GEMM (deterministic k-splits) --------------------
__global__ void k_fc(int which, const float* __restrict__ W, int K, int Ncol) {
    const float* A = (which == 0) ? (const float*)g_feat
                   : (which == 1) ? (const float*)g_e0 : (const float*)g_e1;
    __shared__ float sa[16][128];
    int tid = threadIdx.x;
    int j = blockIdx.x * 128 + tid;
    int kslab = K / gridDim.y;
    int k0 = blockIdx.y * kslab;
    float acc[16];
#pragma unroll
    for (int bi = 0; bi < 16; bi++) acc[bi] = 0.f;
    for (int kt = k0; kt < k0 + kslab; kt += 128) {
#pragma unroll
        for (int i = 0; i < 16; i++) sa[i][tid] = A[i * K + kt + tid];
        __syncthreads();
#pragma unroll 8
        for (int kk = 0; kk < 128; kk++) {
            float wv = W[(size_t)(kt + kk) * Ncol + j];
#pragma unroll
            for (int bi = 0; bi < 16; bi++) acc[bi] += sa[bi][kk] * wv;
        }
        __syncthreads();
    }
#pragma unroll
    for (int bi = 0; bi < 16; bi++)
        g_part[((size_t)blockIdx.y * 16 + bi) * Ncol + j] = acc[bi];
}

__global__ void k_fcsum(int which, const float* __restrict__ bias,
                        int Ncol, int nsplit) {
    float* C = (which == 0) ? g_e0 : (which == 1) ? g_e1 : g_e2;
    int i = blockIdx.x * blockDim.x + threadIdx.x;
    if (i < 16 * Ncol) {
        float s = 0.f;
        for (int p = 0; p < nsplit; p++) s += g_part[(size_t)p * 16 * Ncol + i];
        C[i] = elu1(s + bias[i % Ncol]);
    }
}

__global__ void k_last(const float* __restrict__ lw, const float* __restrict__ lb,
                       float* __restrict__ out, int out_n) {
    int t = threadIdx.x;
    if (t < 32 && t < out_n) {
        int bi = t >> 1, o = t & 1;
        float a = 0.f;
        for (int k = 0; k < OMIC_; k++) a += g_e2[bi * OMIC_ + k] * lw[k * 2 + o];
        out[t] = a + lb[o];
    }
}

// ---------------- driver ------------------------------------------------------
extern "C" void kernel_launch(void* const* d_in, const int* in_sizes, int n_in,
                              void* d_out, int out_size) {
    const float* x   = (const float*)d_in[0];
    const void*  ei  = d_in[1];
    const float* w1  = (const float*)d_in[2];
    const float* as1 = (const float*)d_in[3];
    const float* ad1 = (const float*)d_in[4];
    const float* b1  = (const float*)d_in[5];
    const float* p1w = (const float*)d_in[6];
    const float* p1b = (const float*)d_in[7];
    const float* w2  = (const float*)d_in[8];
    const float* as2 = (const float*)d_in[9];
    const float* ad2 = (const float*)d_in[10];
    const float* b2  = (const float*)d_in[11];
    const float* p2w = (const float*)d_in[12];
    const float* p2b = (const float*)d_in[13];
    const float* lnw = (const float*)d_in[14];
    const float* lnb = (const float*)d_in[15];
    const float* e0w = (const float*)d_in[16];
    const float* e0b = (const float*)d_in[17];
    const float* e1w = (const float*)d_in[18];
    const float* e1b = (const float*)d_in[19];
    const float* e2w = (const float*)d_in[20];
    const float* e2b = (const float*)d_in[21];
    const float* lw  = (const float*)d_in[22];
    const float* lb  = (const float*)d_in[23];
    float* out = (float*)d_out;

    k_detect<<<1, 32>>>(ei);                                   // 1
    k_zero<<<128, 256>>>();                                    // 2
    k_deg<<<E_ / 256, 256>>>(ei);                              // 3
    k_gemm_tc<<<dim3(NT_ / 128, 2), 256>>>(x, 0, w1, INCH_);   // 4 <- profiled
    k_scan1<<<128, 256>>>();                                   // 5
    k_scan2<<<1, 128>>>();                                     // 6
    k_scan3<<<128, 256>>>();                                   // 7
    k_scatter<<<E_ / 256, 256>>>(ei);                          // 8
    k_sortseg<<<NT_ / 256, 256>>>();                           // 9
    k_attn<<<NT_ / 8, 256>>>(as1, ad1);                        // 10
    k_agg<<<NT_ / 8, 256>>>(b1, p1w, p1b, 1, 1);               // 11

    k_gemm_tc<<<dim3(NT_ / 128, 2), 256>>>(nullptr, 1, w2, HC_);
    k_attn<<<NT_ / 8, 256>>>(as2, ad2);
    k_agg<<<NT_ / 8, 256>>>(b2, p2w, p2b, 0, 2);

    k_x0<<<NT_ / 8, 256>>>(x);
    k_ln<<<48, 256>>>(lnw, lnb);

    k_fc<<<dim3(FC0_ / 128, 12), 128>>>(0, e0w, 3 * N_, FC0_);
    k_fcsum<<<(16 * FC0_ + 255) / 256, 256>>>(0, e0b, FC0_, 12);
    k_fc<<<dim3(FC1_ / 128, 4), 128>>>(1, e1w, FC0_, FC1_);
    k_fcsum<<<(16 * FC1_ + 255) / 256, 256>>>(1, e1b, FC1_, 4);
    k_fc<<<dim3(OMIC_ / 128, 4), 128>>>(2, e2w, FC1_, OMIC_);
    k_fcsum<<<(16 * OMIC_ + 255) / 256, 256>>>(2, e2b, OMIC_, 4);
    k_last<<<1, 32>>>(lw, lb, out, out_size);
}